// round 15
// baseline (speedup 1.0000x reference)
#include <cuda_runtime.h>
#include <math.h>

#define Bb 32
#define Tt 8
#define Nn 150
#define Ff 16
#define Hh 32
#define Rr 4
#define Ee 16

#define NP 160                     // K dim padded (zeroed)
#define NR 192                     // A row dim padded
#define RP 192                     // output row padding stride
#define JB 2560                    // agg1 col space: X(512) | H0(1024) | H1(1024)
#define JG 2048                    // agg2 col space: G0(1024) | G1(1024)
#define XT (NP*512)
#define HSZ (Bb*Nn*Hh*Rr)

// slots: 0=f0, 1=Re f1, 2=Im f1, 3=f2, 4=slot1+slot2 (Karatsuba)
__device__ float g_At  [5*NP*NR];
__device__ float g_W   [2*3*64*128];      // [l*3+gate][c][h][slot4] (float4 per (c,h))
__device__ float g_Xall[5*Tt*NP*512];
__device__ float g_Hf  [5*NP*2048];
__device__ float g_AXH [5*RP*JB];
__device__ float g_Gf  [5*NP*2048];
__device__ float g_AG  [5*RP*JG];
__device__ float g_Z   [2*HSZ];
__device__ float g_H   [4*HSZ];

__device__ __forceinline__ float fsig(float x){ return __fdividef(1.f, 1.f + __expf(-x)); }
__device__ __forceinline__ float ftanh(float x){
    float e = __expf(2.f*x);
    return __fdividef(e - 1.f, e + 1.f);
}

// ---------------------------------------------------------------------------
__global__ void adj_kernel(const float* __restrict__ U) {
    cudaGridDependencySynchronize();
    __shared__ float sUf[Ee][4];
    __shared__ float red[256];
    int n = blockIdx.x;
    int tid = threadIdx.x;
    if (tid < Ee*4) {
        int e = tid >> 2, s = tid & 3;
        const float* p = U + (n*Ee + e)*4;
        float u0=p[0],u1=p[1],u2=p[2],u3=p[3];
        float v;
        if (s==0) v = u0+u1+u2+u3;
        else if (s==1) v = u0-u2;
        else if (s==2) v = u3-u1;
        else v = u0-u1+u2-u3;
        sUf[e][s] = v;
    }
    __syncthreads();
    int m = tid;
    float a0=0.f,a1=0.f,a2=0.f,a3=0.f;
    if (m < Nn) {
        float P0=0.f,P1r=0.f,P1i=0.f,P2=0.f;
        #pragma unroll
        for (int e=0;e<Ee;e++){
            const float* p = U + (m*Ee + e)*4;
            float u0=p[0],u1=p[1],u2=p[2],u3=p[3];
            float m0=u0+u1+u2+u3, m1r=u0-u2, m1i=u3-u1, m2=u0-u1+u2-u3;
            float q0=sUf[e][0], q1r=sUf[e][1], q1i=sUf[e][2], q2=sUf[e][3];
            P0  += q0*m0;
            P2  += q2*m2;
            P1r += q1r*m1r - q1i*m1i;
            P1i += q1r*m1i + q1i*m1r;
        }
        a0 = fmaxf(0.25f*(P0 + P2 + 2.f*P1r), 0.f);
        a1 = fmaxf(0.25f*(P0 - P2 - 2.f*P1i), 0.f);
        a2 = fmaxf(0.25f*(P0 + P2 - 2.f*P1r), 0.f);
        a3 = fmaxf(0.25f*(P0 - P2 + 2.f*P1i), 0.f);
    }
    float av[4] = {a0,a1,a2,a3};
    float v[4];
    for (int r=0;r<4;r++){
        red[tid] = (m<Nn) ? av[r] : -1e30f; __syncthreads();
        for (int s=128;s>0;s>>=1){ if (tid<s) red[tid]=fmaxf(red[tid],red[tid+s]); __syncthreads(); }
        float mx = red[0]; __syncthreads();
        float ex = (m<Nn) ? expf(av[r]-mx) : 0.f;
        red[tid] = ex; __syncthreads();
        for (int s=128;s>0;s>>=1){ if (tid<s) red[tid]+=red[tid+s]; __syncthreads(); }
        float sm = red[0]; __syncthreads();
        v[r] = ex / sm;
    }
    if (m < Nn) {
        float s1 = v[0]-v[2];
        float s2 = v[3]-v[1];
        g_At[0*NP*NR + m*NR + n] = v[0]+v[1]+v[2]+v[3];
        g_At[1*NP*NR + m*NR + n] = s1;
        g_At[2*NP*NR + m*NR + n] = s2;
        g_At[3*NP*NR + m*NR + n] = v[0]-v[1]+v[2]-v[3];
        g_At[4*NP*NR + m*NR + n] = s1 + s2;
    }
}

// ---------------------------------------------------------------------------
__global__ void wprep_kernel(const float* wxz0,const float* wxr0,const float* wxh0,
                             const float* whz0,const float* whr0,
                             const float* wxz1,const float* wxr1,const float* wxh1,
                             const float* whz1,const float* whr1) {
    cudaGridDependencySynchronize();
    int idx = blockIdx.x*blockDim.x + threadIdx.x;
    if (idx >= 2*3*64*32) return;
    int h = idx & 31;
    int c = (idx >> 5) & 63;
    int g = (idx >> 11) % 3;
    int l = idx / (3*64*32);
    int Fin = l ? 32 : 16;
    int C = Fin + 32;
    float w[4] = {0.f,0.f,0.f,0.f};
    if (c < C) {
        bool xp = c < Fin;
        int row = xp ? c : (c - Fin);
        const float* src;
        if (l == 0)
            src = (g==0) ? (xp? wxz0: whz0) : (g==1) ? (xp? wxr0: whr0) : (xp? wxh0: whr0);
        else
            src = (g==0) ? (xp? wxz1: whz1) : (g==1) ? (xp? wxr1: whr1) : (xp? wxh1: whr1);
        const float* p = src + (row*Hh + h)*4;
        float u0=p[0],u1=p[1],u2=p[2],u3=p[3];
        w[0]=u0+u1+u2+u3; w[1]=u0-u2; w[2]=u3-u1; w[3]=u0-u1+u2-u3;
    }
    int base = ((l*3+g)*64 + c)*128 + h*4;
    #pragma unroll
    for (int s=0;s<4;s++) g_W[base + s] = w[s];
}

// ---------------------------------------------------------------------------
__global__ void xprep_kernel(const float* __restrict__ X){
    cudaGridDependencySynchronize();
    int idx = blockIdx.x*blockDim.x + threadIdx.x;
    if (idx >= Tt*Nn*512) return;
    int col = idx & 511;
    int rest = idx >> 9;
    int n = rest % Nn;
    int t = rest / Nn;
    int b = col >> 4, f = col & 15;
    const float4 v = *reinterpret_cast<const float4*>(
        X + ((((size_t)b*Tt + t)*Nn + n)*Ff + f)*4);
    float s1 = v.x - v.z, s2 = v.w - v.y;
    size_t base = ((size_t)t*NP + n)*512 + col;
    const size_t SS = (size_t)Tt*NP*512;
    g_Xall[0*SS + base] = v.x+v.y+v.z+v.w;
    g_Xall[1*SS + base] = s1;
    g_Xall[2*SS + base] = s2;
    g_Xall[3*SS + base] = v.x-v.y+v.z-v.w;
    g_Xall[4*SS + base] = s1 + s2;
}

// ---------------------------------------------------------------------------
// Aggregation GEMM: 64x64 tile, 256 threads, 4x4/thread, double-buffered, FFMA2.
// ---------------------------------------------------------------------------
__global__ __launch_bounds__(256) void agg6_kernel(
    const float* __restrict__ B0, int ld0, size_t sst0, int xlim,
    const float* __restrict__ B1, int ld1, size_t sst1,
    float* __restrict__ Out, int ldo, size_t ssto, int bxOff)
{
    cudaGridDependencySynchronize();
    int s = blockIdx.z;
    int colG = (bxOff + blockIdx.x)*64;
    const float* Bp; int ld; size_t sst; int colL;
    if (colG < xlim){ Bp=B0; ld=ld0; sst=sst0; colL=colG; }
    else            { Bp=B1; ld=ld1; sst=sst1; colL=colG-xlim; }
    const float* A = g_At + (size_t)s*NP*NR;
    const float* X = Bp + s*sst + colL;
    float* O = Out + s*ssto + colG;
    int nBase = blockIdx.y*64;

    __shared__ float sA[2][16][64];
    __shared__ float sB[2][16][64];
    int tid = threadIdx.x;
    int tx = tid & 15, ty = tid >> 4;
    int lr = tid >> 4, lc = (tid & 15)*4;

    const float* Ap = A + (size_t)lr*NR + nBase + lc;
    const float* Bq = X + (size_t)lr*ld + lc;

    float4 ra = *reinterpret_cast<const float4*>(Ap);
    float4 rb = *reinterpret_cast<const float4*>(Bq);
    *reinterpret_cast<float4*>(&sA[0][lr][lc]) = ra;
    *reinterpret_cast<float4*>(&sB[0][lr][lc]) = rb;
    __syncthreads();

    unsigned long long acc2[2][4] = {{0ULL,0ULL,0ULL,0ULL},{0ULL,0ULL,0ULL,0ULL}};

    for (int ch=0; ch<10; ch++){
        int buf = ch&1;
        if (ch<9){
            size_t ko = (size_t)(ch+1)*16;
            ra = *reinterpret_cast<const float4*>(Ap + ko*NR);
            rb = *reinterpret_cast<const float4*>(Bq + ko*ld);
        }
        #pragma unroll
        for (int kk=0;kk<16;kk++){
            float4 a = *reinterpret_cast<const float4*>(&sA[buf][kk][ty*4]);
            float4 b = *reinterpret_cast<const float4*>(&sB[buf][kk][tx*4]);
            unsigned long long a01, a23;
            asm("mov.b64 %0, {%1, %2};" : "=l"(a01) : "f"(a.x), "f"(a.y));
            asm("mov.b64 %0, {%1, %2};" : "=l"(a23) : "f"(a.z), "f"(a.w));
            unsigned long long bd0, bd1, bd2, bd3;
            asm("mov.b64 %0, {%1, %1};" : "=l"(bd0) : "f"(b.x));
            asm("mov.b64 %0, {%1, %1};" : "=l"(bd1) : "f"(b.y));
            asm("mov.b64 %0, {%1, %1};" : "=l"(bd2) : "f"(b.z));
            asm("mov.b64 %0, {%1, %1};" : "=l"(bd3) : "f"(b.w));
            asm("fma.rn.f32x2 %0, %1, %2, %0;" : "+l"(acc2[0][0]) : "l"(a01), "l"(bd0));
            asm("fma.rn.f32x2 %0, %1, %2, %0;" : "+l"(acc2[0][1]) : "l"(a01), "l"(bd1));
            asm("fma.rn.f32x2 %0, %1, %2, %0;" : "+l"(acc2[0][2]) : "l"(a01), "l"(bd2));
            asm("fma.rn.f32x2 %0, %1, %2, %0;" : "+l"(acc2[0][3]) : "l"(a01), "l"(bd3));
            asm("fma.rn.f32x2 %0, %1, %2, %0;" : "+l"(acc2[1][0]) : "l"(a23), "l"(bd0));
            asm("fma.rn.f32x2 %0, %1, %2, %0;" : "+l"(acc2[1][1]) : "l"(a23), "l"(bd1));
            asm("fma.rn.f32x2 %0, %1, %2, %0;" : "+l"(acc2[1][2]) : "l"(a23), "l"(bd2));
            asm("fma.rn.f32x2 %0, %1, %2, %0;" : "+l"(acc2[1][3]) : "l"(a23), "l"(bd3));
        }
        if (ch<9){
            int nb = buf^1;
            *reinterpret_cast<float4*>(&sA[nb][lr][lc]) = ra;
            *reinterpret_cast<float4*>(&sB[nb][lr][lc]) = rb;
        }
        __syncthreads();
    }

    float acc[4][4];
    #pragma unroll
    for (int p=0;p<2;p++)
        #pragma unroll
        for (int j=0;j<4;j++){
            float lo, hi;
            asm("mov.b64 {%0, %1}, %2;" : "=f"(lo), "=f"(hi) : "l"(acc2[p][j]));
            acc[2*p][j] = lo;
            acc[2*p+1][j] = hi;
        }
    #pragma unroll
    for (int i=0;i<4;i++){
        int n = nBase + ty*4 + i;
        if (n < Nn)
            *reinterpret_cast<float4*>(O + (size_t)n*ldo + tx*4) =
                make_float4(acc[i][0],acc[i][1],acc[i][2],acc[i][3]);
    }
}

// ---------------------------------------------------------------------------
// Gates templated body: fully unrolled for compile-time C / SEC.
// ---------------------------------------------------------------------------
template<int C, int SEC>
__device__ __forceinline__ void gates_body(float* sX, int n, int bgBase,
    const float* __restrict__ Hs, const float* __restrict__ bias, int sec)
{
    int tid = threadIdx.y*32 + threadIdx.x;
    const size_t SS = (size_t)RP*JB;
    const float* AX = g_AXH + (size_t)n*JB;
    int gcol = SEC ? 1024 : 0;
    #pragma unroll 4
    for (int i=tid;i<4*C*8;i+=128){
        int c = i % C; int r = i / C; int s = r >> 3; int bl = r & 7;
        int b = bgBase + bl;
        int col = (SEC==0) ? ((c<16)?(b*16+c):(512 + b*32 + (c-16)))
                           : ((c<32)?(512 + b*32 + c):(1536 + b*32 + (c-32)));
        float v;
        if (s==0)      v = AX[col];
        else if (s==1) v = AX[SS+col] - AX[2*SS+col];
        else if (s==2) v = AX[4*SS+col] - AX[SS+col] - AX[2*SS+col];
        else           v = AX[3*SS+col];
        sX[(s*C + c)*9 + bl] = v;
    }
    __syncthreads();

    int h = threadIdx.x, bt = threadIdx.y;
    const float4* W4 = reinterpret_cast<const float4*>(g_W);
    const float4* Wz = W4 + (size_t)(sec*3+0)*2048 + h;
    const float4* Wr = W4 + (size_t)(sec*3+1)*2048 + h;
    float yz0[2]={},yz1[2]={},yz2[2]={},yz3[2]={};
    float yr0[2]={},yr1[2]={},yr2[2]={},yr3[2]={};
    #pragma unroll
    for (int c=0;c<C;c++){
        float4 wz = Wz[c*32];
        float4 wr = Wr[c*32];
        #pragma unroll
        for (int bb=0;bb<2;bb++){
            int bl = bt*2+bb;
            float x0 =sX[(0*C+c)*9+bl], x1r=sX[(1*C+c)*9+bl],
                  x1i=sX[(2*C+c)*9+bl], x2 =sX[(3*C+c)*9+bl];
            yz0[bb]+=x0*wz.x; yz1[bb]+=x1r*wz.y - x1i*wz.z;
            yz2[bb]+=x1r*wz.z + x1i*wz.y; yz3[bb]+=x2*wz.w;
            yr0[bb]+=x0*wr.x; yr1[bb]+=x1r*wr.y - x1i*wr.z;
            yr2[bb]+=x1r*wr.z + x1i*wr.y; yr3[bb]+=x2*wr.w;
        }
    }
    float bz[4], br[4];
    #pragma unroll
    for (int r=0;r<4;r++){ bz[r]=bias[h*4+r]; br[r]=bias[128+h*4+r]; }
    float* Z = g_Z + (size_t)sec*HSZ;
    const size_t GS = (size_t)NP*2048;
    #pragma unroll
    for (int bb=0;bb<2;bb++){
        int b = bgBase + bt*2 + bb;
        float vz[4] = {0.25f*(yz0[bb]+yz3[bb]+2.f*yz1[bb]), 0.25f*(yz0[bb]-yz3[bb]-2.f*yz2[bb]),
                       0.25f*(yz0[bb]+yz3[bb]-2.f*yz1[bb]), 0.25f*(yz0[bb]-yz3[bb]+2.f*yz2[bb])};
        float vr[4] = {0.25f*(yr0[bb]+yr3[bb]+2.f*yr1[bb]), 0.25f*(yr0[bb]-yr3[bb]-2.f*yr2[bb]),
                       0.25f*(yr0[bb]+yr3[bb]-2.f*yr1[bb]), 0.25f*(yr0[bb]-yr3[bb]+2.f*yr2[bb])};
        size_t hoff = (((size_t)b*Nn + n)*Hh + h)*4;
        float4 hs4 = Hs ? *reinterpret_cast<const float4*>(Hs + hoff) : make_float4(0,0,0,0);
        float hsv[4] = {hs4.x,hs4.y,hs4.z,hs4.w};
        float g[4], zv[4];
        #pragma unroll
        for (int r=0;r<4;r++){
            zv[r] = fsig(vz[r] + bz[r]);
            float rg = fsig(vr[r] + br[r]);
            g[r] = rg*hsv[r];
        }
        *reinterpret_cast<float4*>(Z + hoff) = make_float4(zv[0],zv[1],zv[2],zv[3]);
        size_t gb = (size_t)n*2048 + gcol + b*Hh + h;
        float s1 = g[0]-g[2], s2 = g[3]-g[1];
        g_Gf[0*GS + gb] = g[0]+g[1]+g[2]+g[3];
        g_Gf[1*GS + gb] = s1;
        g_Gf[2*GS + gb] = s2;
        g_Gf[3*GS + gb] = g[0]-g[1]+g[2]-g[3];
        g_Gf[4*GS + gb] = s1 + s2;
    }
}

__global__ void gates6_kernel(int secBase,
    const float* __restrict__ HsA, const float* __restrict__ biasA,
    const float* __restrict__ HsB, const float* __restrict__ biasB)
{
    cudaGridDependencySynchronize();
    __shared__ float sX[4*64*9];
    int n = blockIdx.x;
    int sec = secBase + blockIdx.y;
    int bgBase = blockIdx.z * 8;
    const float* Hs   = blockIdx.y ? HsB : HsA;
    const float* bias = blockIdx.y ? biasB : biasA;
    if (sec == 0) gates_body<48,0>(sX, n, bgBase, Hs, bias, sec);
    else          gates_body<64,1>(sX, n, bgBase, Hs, bias, sec);
}

// ---------------------------------------------------------------------------
// Ht templated body.
// ---------------------------------------------------------------------------
template<int FIN, int SEC>
__device__ __forceinline__ void ht_body(float* sXx, float* sG, int n, int bgBase, int t,
    const float* __restrict__ Hs, const float* __restrict__ bias, int sec,
    float* __restrict__ Hnew, float* __restrict__ outp, float* __restrict__ tailp)
{
    int tid = threadIdx.y*32 + threadIdx.x;
    const size_t SS = (size_t)RP*JB;
    const size_t AS = (size_t)RP*JG;
    int gcol = SEC ? 1024 : 0;
    int hbase= SEC ? 1024 : 0;
    const float* AX = g_AXH + (size_t)n*JB;
    const float* AG = g_AG + (size_t)n*JG + gcol;
    #pragma unroll 4
    for (int i=tid;i<4*FIN*8;i+=128){
        int c = i % FIN; int r = i / FIN; int s = r >> 3; int bl = r & 7;
        int b = bgBase + bl;
        int col = (SEC==0) ? (b*16+c) : (512 + b*32 + c);
        float v;
        if (s==0)      v = AX[col];
        else if (s==1) v = AX[SS+col] - AX[2*SS+col];
        else if (s==2) v = AX[4*SS+col] - AX[SS+col] - AX[2*SS+col];
        else           v = AX[3*SS+col];
        sXx[(s*FIN + c)*9 + bl] = v;
    }
    #pragma unroll 4
    for (int i=tid;i<4*32*8;i+=128){
        int c = i & 31; int r = i >> 5; int s = r >> 3; int bl = r & 7;
        int b = bgBase + bl;
        int col = b*Hh + c;
        float v;
        if (s==0)      v = AG[col];
        else if (s==1) v = AG[AS+col] - AG[2*AS+col];
        else if (s==2) v = AG[4*AS+col] - AG[AS+col] - AG[2*AS+col];
        else           v = AG[3*AS+col];
        sG[(s*32 + c)*9 + bl] = v;
    }
    __syncthreads();

    int h = threadIdx.x, bt = threadIdx.y;
    const float4* Wh = reinterpret_cast<const float4*>(g_W) + (size_t)(sec*3+2)*2048 + h;
    float y0[2]={},y1[2]={},y2[2]={},y3[2]={};
    #pragma unroll
    for (int c=0;c<FIN;c++){
        float4 w = Wh[c*32];
        #pragma unroll
        for (int bb=0;bb<2;bb++){
            int bl = bt*2+bb;
            float x0 =sXx[(0*FIN+c)*9+bl], x1r=sXx[(1*FIN+c)*9+bl],
                  x1i=sXx[(2*FIN+c)*9+bl], x2 =sXx[(3*FIN+c)*9+bl];
            y0[bb]+=x0*w.x; y1[bb]+=x1r*w.y - x1i*w.z;
            y2[bb]+=x1r*w.z + x1i*w.y; y3[bb]+=x2*w.w;
        }
    }
    #pragma unroll
    for (int c=0;c<Hh;c++){
        float4 w = Wh[(FIN+c)*32];
        #pragma unroll
        for (int bb=0;bb<2;bb++){
            int bl = bt*2+bb;
            float x0 =sG[(0*32+c)*9+bl], x1r=sG[(1*32+c)*9+bl],
                  x1i=sG[(2*32+c)*9+bl], x2 =sG[(3*32+c)*9+bl];
            y0[bb]+=x0*w.x; y1[bb]+=x1r*w.y - x1i*w.z;
            y2[bb]+=x1r*w.z + x1i*w.y; y3[bb]+=x2*w.w;
        }
    }
    float bh[4];
    #pragma unroll
    for (int r=0;r<4;r++) bh[r] = bias[256 + h*4 + r];
    const float* Z = g_Z + (size_t)sec*HSZ;
    const size_t HS2 = (size_t)NP*2048;
    #pragma unroll
    for (int bb=0;bb<2;bb++){
        int b = bgBase + bt*2 + bb;
        float v[4] = {0.25f*(y0[bb]+y3[bb]+2.f*y1[bb]), 0.25f*(y0[bb]-y3[bb]-2.f*y2[bb]),
                      0.25f*(y0[bb]+y3[bb]-2.f*y1[bb]), 0.25f*(y0[bb]-y3[bb]+2.f*y2[bb])};
        size_t hoff = (((size_t)b*Nn+n)*Hh + h)*4;
        float4 z4 = *reinterpret_cast<const float4*>(Z + hoff);
        float zv[4] = {z4.x,z4.y,z4.z,z4.w};
        float4 hs4 = Hs ? *reinterpret_cast<const float4*>(Hs + hoff) : make_float4(0,0,0,0);
        float hsv[4] = {hs4.x,hs4.y,hs4.z,hs4.w};
        float hn[4];
        #pragma unroll
        for (int r=0;r<4;r++){
            float ht = ftanh(v[r] + bh[r]);
            hn[r] = zv[r]*hsv[r] + (1.f-zv[r])*ht;
        }
        float4 hv = make_float4(hn[0],hn[1],hn[2],hn[3]);
        *reinterpret_cast<float4*>(Hnew + hoff) = hv;
        if (outp)
            *reinterpret_cast<float4*>(outp + (((size_t)b*Tt + t)*Nn + n)*(Hh*4) + h*4) = hv;
        if (tailp)
            *reinterpret_cast<float4*>(tailp + hoff) = hv;
        size_t hb = (size_t)n*2048 + hbase + b*Hh + h;
        float s1 = hn[0]-hn[2], s2 = hn[3]-hn[1];
        g_Hf[0*HS2 + hb] = hn[0]+hn[1]+hn[2]+hn[3];
        g_Hf[1*HS2 + hb] = s1;
        g_Hf[2*HS2 + hb] = s2;
        g_Hf[3*HS2 + hb] = hn[0]-hn[1]+hn[2]-hn[3];
        g_Hf[4*HS2 + hb] = s1 + s2;
    }
}

__global__ void ht6_kernel(int secBase, int t,
    const float* __restrict__ HsA, const float* __restrict__ biasA,
    float* __restrict__ HnewA, float* __restrict__ outA, float* __restrict__ tailA,
    const float* __restrict__ HsB, const float* __restrict__ biasB,
    float* __restrict__ HnewB, float* __restrict__ outB, float* __restrict__ tailB)
{
    cudaGridDependencySynchronize();
    __shared__ float sXx[4*32*9];
    __shared__ float sG[4*32*9];
    int n = blockIdx.x;
    int sec = secBase + blockIdx.y;
    int bgBase = blockIdx.z * 8;
    const float* Hs   = blockIdx.y ? HsB : HsA;
    const float* bias = blockIdx.y ? biasB : biasA;
    float* Hnew = blockIdx.y ? HnewB : HnewA;
    float* outp = blockIdx.y ? outB : outA;
    float* tailp= blockIdx.y ? tailB : tailA;
    if (sec == 0) ht_body<16,0>(sXx, sG, n, bgBase, t, Hs, bias, sec, Hnew, outp, tailp);
    else          ht_body<32,1>(sXx, sG, n, bgBase, t, Hs, bias, sec, Hnew, outp, tailp);
}

// ---------------------------------------------------------------------------
template <typename K, typename... Args>
static inline void pdl(K kern, dim3 g, dim3 b, Args... args){
    cudaLaunchConfig_t cfg = {};
    cfg.gridDim = g;
    cfg.blockDim = b;
    cfg.dynamicSmemBytes = 0;
    cfg.stream = 0;
    cudaLaunchAttribute attr[1];
    attr[0].id = cudaLaunchAttributeProgrammaticStreamSerialization;
    attr[0].val.programmaticStreamSerializationAllowed = 1;
    cfg.attrs = attr;
    cfg.numAttrs = 1;
    cudaLaunchKernelEx(&cfg, kern, args...);
}

// ---------------------------------------------------------------------------
extern "C" void kernel_launch(void* const* d_in, const int* in_sizes, int n_in,
                              void* d_out, int out_size) {
    (void)in_sizes; (void)n_in;
    const float* inputs = (const float*)d_in[0];
    const float* U      = (const float*)d_in[1];
    const float* B0p    = (const float*)d_in[7];
    const float* B1p    = (const float*)d_in[13];
    float* out = (float*)d_out;
    const int OUTSZ = Bb*Tt*Nn*Hh*Rr;
    float* tail = (out_size >= OUTSZ + 2*HSZ) ? (out + OUTSZ) : nullptr;

    void* p;
    cudaGetSymbolAddress(&p, g_At);   float* Atp  = (float*)p;
    cudaGetSymbolAddress(&p, g_Xall); float* Xall = (float*)p;
    cudaGetSymbolAddress(&p, g_Hf);   float* Hf   = (float*)p;
    cudaGetSymbolAddress(&p, g_AXH);  float* AXH  = (float*)p;
    cudaGetSymbolAddress(&p, g_Gf);   float* Gfp  = (float*)p;
    cudaGetSymbolAddress(&p, g_AG);   float* AG   = (float*)p;
    cudaGetSymbolAddress(&p, g_H);    float* Hb   = (float*)p;
    float* H0[2] = {Hb,          Hb +   HSZ};
    float* H1[2] = {Hb + 2*HSZ,  Hb + 3*HSZ};

    cudaMemsetAsync(Atp,  0, sizeof(float)*5*NP*NR);
    cudaMemsetAsync(Xall, 0, sizeof(float)*5*Tt*NP*512);
    cudaMemsetAsync(Hf,   0, sizeof(float)*5*NP*2048);
    cudaMemsetAsync(Gfp,  0, sizeof(float)*5*NP*2048);
    cudaMemsetAsync(AG,   0, sizeof(float)*5*RP*JG);
    cudaMemsetAsync(AXH,  0, sizeof(float)*5*RP*JB);

    pdl(adj_kernel, dim3(Nn), dim3(256), U);
    pdl(wprep_kernel, dim3(48), dim3(256),
        (const float*)d_in[2], (const float*)d_in[3], (const float*)d_in[4],
        (const float*)d_in[5], (const float*)d_in[6],
        (const float*)d_in[8], (const float*)d_in[9], (const float*)d_in[10],
        (const float*)d_in[11], (const float*)d_in[12]);
    pdl(xprep_kernel, dim3((Tt*Nn*512+255)/256), dim3(256), inputs);

    const size_t XSST = (size_t)Tt*XT;
    const size_t HSST = (size_t)NP*2048;
    const size_t AXS  = (size_t)RP*JB;
    const size_t AGS  = (size_t)RP*JG;
    dim3 blkG(32,4);

    // ---- t = 0, layer0 (H cols of AXH zero via memset) ----
    pdl(agg6_kernel, dim3(8,3,5), dim3(256),
        (const float*)Xall, 512, XSST, 512, (const float*)Hf, (int)JG, HSST,
        AXH, (int)JB, AXS, 0);
    pdl(gates6_kernel, dim3(Nn,1,4), blkG,
        0, (const float*)nullptr, B0p, (const float*)nullptr, B0p);
    pdl(ht6_kernel, dim3(Nn,1,4), blkG,
        0, 0,
        (const float*)nullptr, B0p, H0[1], (float*)nullptr, (float*)nullptr,
        (const float*)nullptr, B0p, H0[1], (float*)nullptr, (float*)nullptr);
    // A @ fft(H0(t0)) for layer1's t0 input (cols 512..1536 -> tiles 8..23)
    pdl(agg6_kernel, dim3(16,3,5), dim3(256),
        (const float*)Xall, 512, XSST, 512, (const float*)Hf, (int)JG, HSST,
        AXH, (int)JB, AXS, 8);
    pdl(gates6_kernel, dim3(Nn,1,4), blkG,
        1, (const float*)nullptr, B1p, (const float*)nullptr, B1p);
    pdl(ht6_kernel, dim3(Nn,1,4), blkG,
        1, 0,
        (const float*)nullptr, B1p, H1[1], out, (float*)nullptr,
        (const float*)nullptr, B1p, H1[1], out, (float*)nullptr);

    // ---- t = 1..7 ----
    int c0 = 1, c1 = 1;
    for (int t=1; t<Tt; t++){
        float* tl0 = (t==Tt-1 && tail) ? tail        : nullptr;
        float* tl1 = (t==Tt-1 && tail) ? tail + HSZ  : nullptr;
        const float* Xt = Xall + (size_t)t*XT;
        pdl(agg6_kernel, dim3(40,3,5), dim3(256),
            Xt, 512, XSST, 512, (const float*)Hf, (int)JG, HSST,
            AXH, (int)JB, AXS, 0);
        pdl(gates6_kernel, dim3(Nn,2,4), blkG,
            0, (const float*)H0[c0], B0p, (const float*)H1[c1], B1p);
        pdl(agg6_kernel, dim3(32,3,5), dim3(256),
            (const float*)Gfp, (int)JG, HSST, (1<<30), (const float*)Gfp, (int)JG, HSST,
            AG, (int)JG, AGS, 0);
        pdl(ht6_kernel, dim3(Nn,2,4), blkG,
            0, t,
            (const float*)H0[c0], B0p, H0[c0^1], (float*)nullptr, tl0,
            (const float*)H1[c1], B1p, H1[c1^1], out,             tl1);
        c0 ^= 1; c1 ^= 1;
    }
}

// round 16
// speedup vs baseline: 1.0318x; 1.0318x over previous
#include <cuda_runtime.h>
#include <math.h>

#define Bb 32
#define Tt 8
#define Nn 150
#define Ff 16
#define Hh 32
#define Rr 4
#define Ee 16

#define NP 160                     // K dim padded (zeroed)
#define NR 192                     // A row dim padded
#define RP 192                     // output row padding stride
#define JB 2560                    // agg1 col space: X(512) | H0(1024) | H1(1024)
#define JG 2048                    // agg2 col space: G0(1024) | G1(1024)
#define XT (NP*512)
#define HSZ (Bb*Nn*Hh*Rr)

// slots: 0=f0, 1=Re f1, 2=Im f1, 3=f2, 4=slot1+slot2 (Karatsuba)
__device__ float g_At  [5*NP*NR];
__device__ float g_W   [2*3*64*128];      // [l*3+gate][c][h][slot4] (float4 per (c,h))
__device__ float g_Xall[5*Tt*NP*512];
__device__ float g_Hf  [5*NP*2048];
__device__ float g_AXH [5*RP*JB];
__device__ float g_Gf  [5*NP*2048];
__device__ float g_AG  [5*RP*JG];
__device__ float g_Z   [2*HSZ];
__device__ float g_H   [4*HSZ];

__device__ __forceinline__ float fsig(float x){ return __fdividef(1.f, 1.f + __expf(-x)); }
__device__ __forceinline__ float ftanh(float x){
    float e = __expf(2.f*x);
    return __fdividef(e - 1.f, e + 1.f);
}

// ---------------------------------------------------------------------------
__global__ void adj_kernel(const float* __restrict__ U) {
    cudaGridDependencySynchronize();
    __shared__ float sUf[Ee][4];
    __shared__ float red[256];
    int n = blockIdx.x;
    int tid = threadIdx.x;
    if (tid < Ee*4) {
        int e = tid >> 2, s = tid & 3;
        const float* p = U + (n*Ee + e)*4;
        float u0=p[0],u1=p[1],u2=p[2],u3=p[3];
        float v;
        if (s==0) v = u0+u1+u2+u3;
        else if (s==1) v = u0-u2;
        else if (s==2) v = u3-u1;
        else v = u0-u1+u2-u3;
        sUf[e][s] = v;
    }
    __syncthreads();
    int m = tid;
    float a0=0.f,a1=0.f,a2=0.f,a3=0.f;
    if (m < Nn) {
        float P0=0.f,P1r=0.f,P1i=0.f,P2=0.f;
        #pragma unroll
        for (int e=0;e<Ee;e++){
            const float* p = U + (m*Ee + e)*4;
            float u0=p[0],u1=p[1],u2=p[2],u3=p[3];
            float m0=u0+u1+u2+u3, m1r=u0-u2, m1i=u3-u1, m2=u0-u1+u2-u3;
            float q0=sUf[e][0], q1r=sUf[e][1], q1i=sUf[e][2], q2=sUf[e][3];
            P0  += q0*m0;
            P2  += q2*m2;
            P1r += q1r*m1r - q1i*m1i;
            P1i += q1r*m1i + q1i*m1r;
        }
        a0 = fmaxf(0.25f*(P0 + P2 + 2.f*P1r), 0.f);
        a1 = fmaxf(0.25f*(P0 - P2 - 2.f*P1i), 0.f);
        a2 = fmaxf(0.25f*(P0 + P2 - 2.f*P1r), 0.f);
        a3 = fmaxf(0.25f*(P0 - P2 + 2.f*P1i), 0.f);
    }
    float av[4] = {a0,a1,a2,a3};
    float v[4];
    for (int r=0;r<4;r++){
        red[tid] = (m<Nn) ? av[r] : -1e30f; __syncthreads();
        for (int s=128;s>0;s>>=1){ if (tid<s) red[tid]=fmaxf(red[tid],red[tid+s]); __syncthreads(); }
        float mx = red[0]; __syncthreads();
        float ex = (m<Nn) ? expf(av[r]-mx) : 0.f;
        red[tid] = ex; __syncthreads();
        for (int s=128;s>0;s>>=1){ if (tid<s) red[tid]+=red[tid+s]; __syncthreads(); }
        float sm = red[0]; __syncthreads();
        v[r] = ex / sm;
    }
    if (m < Nn) {
        float s1 = v[0]-v[2];
        float s2 = v[3]-v[1];
        g_At[0*NP*NR + m*NR + n] = v[0]+v[1]+v[2]+v[3];
        g_At[1*NP*NR + m*NR + n] = s1;
        g_At[2*NP*NR + m*NR + n] = s2;
        g_At[3*NP*NR + m*NR + n] = v[0]-v[1]+v[2]-v[3];
        g_At[4*NP*NR + m*NR + n] = s1 + s2;
    }
}

// ---------------------------------------------------------------------------
__global__ void wprep_kernel(const float* wxz0,const float* wxr0,const float* wxh0,
                             const float* whz0,const float* whr0,
                             const float* wxz1,const float* wxr1,const float* wxh1,
                             const float* whz1,const float* whr1) {
    cudaGridDependencySynchronize();
    int idx = blockIdx.x*blockDim.x + threadIdx.x;
    if (idx >= 2*3*64*32) return;
    int h = idx & 31;
    int c = (idx >> 5) & 63;
    int g = (idx >> 11) % 3;
    int l = idx / (3*64*32);
    int Fin = l ? 32 : 16;
    int C = Fin + 32;
    float w[4] = {0.f,0.f,0.f,0.f};
    if (c < C) {
        bool xp = c < Fin;
        int row = xp ? c : (c - Fin);
        const float* src;
        if (l == 0)
            src = (g==0) ? (xp? wxz0: whz0) : (g==1) ? (xp? wxr0: whr0) : (xp? wxh0: whr0);
        else
            src = (g==0) ? (xp? wxz1: whz1) : (g==1) ? (xp? wxr1: whr1) : (xp? wxh1: whr1);
        const float* p = src + (row*Hh + h)*4;
        float u0=p[0],u1=p[1],u2=p[2],u3=p[3];
        w[0]=u0+u1+u2+u3; w[1]=u0-u2; w[2]=u3-u1; w[3]=u0-u1+u2-u3;
    }
    int base = ((l*3+g)*64 + c)*128 + h*4;
    #pragma unroll
    for (int s=0;s<4;s++) g_W[base + s] = w[s];
}

// ---------------------------------------------------------------------------
__global__ void xprep_kernel(const float* __restrict__ X){
    cudaGridDependencySynchronize();
    int idx = blockIdx.x*blockDim.x + threadIdx.x;
    if (idx >= Tt*Nn*512) return;
    int col = idx & 511;
    int rest = idx >> 9;
    int n = rest % Nn;
    int t = rest / Nn;
    int b = col >> 4, f = col & 15;
    const float4 v = *reinterpret_cast<const float4*>(
        X + ((((size_t)b*Tt + t)*Nn + n)*Ff + f)*4);
    float s1 = v.x - v.z, s2 = v.w - v.y;
    size_t base = ((size_t)t*NP + n)*512 + col;
    const size_t SS = (size_t)Tt*NP*512;
    g_Xall[0*SS + base] = v.x+v.y+v.z+v.w;
    g_Xall[1*SS + base] = s1;
    g_Xall[2*SS + base] = s2;
    g_Xall[3*SS + base] = v.x-v.y+v.z-v.w;
    g_Xall[4*SS + base] = s1 + s2;
}

// ---------------------------------------------------------------------------
// Aggregation GEMM: 64x64 tile, 256 threads, 4x4/thread, double-buffered, FFMA2.
// K-chunk 32 (5 chunks): half the syncthreads, double prefetch batch vs chunk-16.
// ---------------------------------------------------------------------------
__global__ __launch_bounds__(256) void agg6_kernel(
    const float* __restrict__ B0, int ld0, size_t sst0, int xlim,
    const float* __restrict__ B1, int ld1, size_t sst1,
    float* __restrict__ Out, int ldo, size_t ssto, int bxOff)
{
    cudaGridDependencySynchronize();
    int s = blockIdx.z;
    int colG = (bxOff + blockIdx.x)*64;
    const float* Bp; int ld; size_t sst; int colL;
    if (colG < xlim){ Bp=B0; ld=ld0; sst=sst0; colL=colG; }
    else            { Bp=B1; ld=ld1; sst=sst1; colL=colG-xlim; }
    const float* A = g_At + (size_t)s*NP*NR;
    const float* X = Bp + s*sst + colL;
    float* O = Out + s*ssto + colG;
    int nBase = blockIdx.y*64;

    __shared__ float sA[2][32][64];
    __shared__ float sB[2][32][64];
    int tid = threadIdx.x;
    int tx = tid & 15, ty = tid >> 4;
    int lr = tid >> 4, lc = (tid & 15)*4;

    const float* Ap = A + (size_t)lr*NR + nBase + lc;
    const float* Bq = X + (size_t)lr*ld + lc;

    float4 ra0 = *reinterpret_cast<const float4*>(Ap);
    float4 ra1 = *reinterpret_cast<const float4*>(Ap + 16*(size_t)NR);
    float4 rb0 = *reinterpret_cast<const float4*>(Bq);
    float4 rb1 = *reinterpret_cast<const float4*>(Bq + 16*(size_t)ld);
    *reinterpret_cast<float4*>(&sA[0][lr   ][lc]) = ra0;
    *reinterpret_cast<float4*>(&sA[0][lr+16][lc]) = ra1;
    *reinterpret_cast<float4*>(&sB[0][lr   ][lc]) = rb0;
    *reinterpret_cast<float4*>(&sB[0][lr+16][lc]) = rb1;
    __syncthreads();

    unsigned long long acc2[2][4] = {{0ULL,0ULL,0ULL,0ULL},{0ULL,0ULL,0ULL,0ULL}};

    for (int ch=0; ch<5; ch++){
        int buf = ch&1;
        if (ch<4){
            size_t ko = (size_t)(ch+1)*32;
            ra0 = *reinterpret_cast<const float4*>(Ap + ko*NR);
            ra1 = *reinterpret_cast<const float4*>(Ap + (ko+16)*NR);
            rb0 = *reinterpret_cast<const float4*>(Bq + ko*ld);
            rb1 = *reinterpret_cast<const float4*>(Bq + (ko+16)*ld);
        }
        #pragma unroll
        for (int kk=0;kk<32;kk++){
            float4 a = *reinterpret_cast<const float4*>(&sA[buf][kk][ty*4]);
            float4 b = *reinterpret_cast<const float4*>(&sB[buf][kk][tx*4]);
            unsigned long long a01, a23;
            asm("mov.b64 %0, {%1, %2};" : "=l"(a01) : "f"(a.x), "f"(a.y));
            asm("mov.b64 %0, {%1, %2};" : "=l"(a23) : "f"(a.z), "f"(a.w));
            unsigned long long bd0, bd1, bd2, bd3;
            asm("mov.b64 %0, {%1, %1};" : "=l"(bd0) : "f"(b.x));
            asm("mov.b64 %0, {%1, %1};" : "=l"(bd1) : "f"(b.y));
            asm("mov.b64 %0, {%1, %1};" : "=l"(bd2) : "f"(b.z));
            asm("mov.b64 %0, {%1, %1};" : "=l"(bd3) : "f"(b.w));
            asm("fma.rn.f32x2 %0, %1, %2, %0;" : "+l"(acc2[0][0]) : "l"(a01), "l"(bd0));
            asm("fma.rn.f32x2 %0, %1, %2, %0;" : "+l"(acc2[0][1]) : "l"(a01), "l"(bd1));
            asm("fma.rn.f32x2 %0, %1, %2, %0;" : "+l"(acc2[0][2]) : "l"(a01), "l"(bd2));
            asm("fma.rn.f32x2 %0, %1, %2, %0;" : "+l"(acc2[0][3]) : "l"(a01), "l"(bd3));
            asm("fma.rn.f32x2 %0, %1, %2, %0;" : "+l"(acc2[1][0]) : "l"(a23), "l"(bd0));
            asm("fma.rn.f32x2 %0, %1, %2, %0;" : "+l"(acc2[1][1]) : "l"(a23), "l"(bd1));
            asm("fma.rn.f32x2 %0, %1, %2, %0;" : "+l"(acc2[1][2]) : "l"(a23), "l"(bd2));
            asm("fma.rn.f32x2 %0, %1, %2, %0;" : "+l"(acc2[1][3]) : "l"(a23), "l"(bd3));
        }
        if (ch<4){
            int nb = buf^1;
            *reinterpret_cast<float4*>(&sA[nb][lr   ][lc]) = ra0;
            *reinterpret_cast<float4*>(&sA[nb][lr+16][lc]) = ra1;
            *reinterpret_cast<float4*>(&sB[nb][lr   ][lc]) = rb0;
            *reinterpret_cast<float4*>(&sB[nb][lr+16][lc]) = rb1;
        }
        __syncthreads();
    }

    float acc[4][4];
    #pragma unroll
    for (int p=0;p<2;p++)
        #pragma unroll
        for (int j=0;j<4;j++){
            float lo, hi;
            asm("mov.b64 {%0, %1}, %2;" : "=f"(lo), "=f"(hi) : "l"(acc2[p][j]));
            acc[2*p][j] = lo;
            acc[2*p+1][j] = hi;
        }
    #pragma unroll
    for (int i=0;i<4;i++){
        int n = nBase + ty*4 + i;
        if (n < Nn)
            *reinterpret_cast<float4*>(O + (size_t)n*ldo + tx*4) =
                make_float4(acc[i][0],acc[i][1],acc[i][2],acc[i][3]);
    }
}

// ---------------------------------------------------------------------------
// Gates: grid (Nn, nSec, 4 batch groups), block (32,4). Thread handles 2 batches.
// float4-packed weights, fast activations. (R14 form — runtime trip counts.)
// ---------------------------------------------------------------------------
__global__ void gates6_kernel(int secBase,
    const float* __restrict__ HsA, const float* __restrict__ biasA,
    const float* __restrict__ HsB, const float* __restrict__ biasB)
{
    cudaGridDependencySynchronize();
    int n = blockIdx.x;
    int sec = secBase + blockIdx.y;
    int bgBase = blockIdx.z * 8;
    const float* Hs   = blockIdx.y ? HsB : HsA;
    const float* bias = blockIdx.y ? biasB : biasA;
    int C    = sec ? 64 : 48;
    int gcol = sec ? 1024 : 0;

    __shared__ float sX[4][64][9];
    int tid = threadIdx.y*32 + threadIdx.x;
    const size_t SS = (size_t)RP*JB;
    const float* AX = g_AXH + (size_t)n*JB;
    for (int i=tid;i<4*C*8;i+=128){
        int c = i % C; int r = i / C; int s = r >> 3; int bl = r & 7;
        int b = bgBase + bl;
        int col = (sec==0) ? ((c<16)?(b*16+c):(512 + b*32 + (c-16)))
                           : ((c<32)?(512 + b*32 + c):(1536 + b*32 + (c-32)));
        float v;
        if (s==0)      v = AX[col];
        else if (s==1) v = AX[SS+col] - AX[2*SS+col];
        else if (s==2) v = AX[4*SS+col] - AX[SS+col] - AX[2*SS+col];
        else           v = AX[3*SS+col];
        sX[s][c][bl] = v;
    }
    __syncthreads();

    int h = threadIdx.x, bt = threadIdx.y;
    const float4* W4 = reinterpret_cast<const float4*>(g_W);
    const float4* Wz = W4 + (size_t)(sec*3+0)*2048 + h;
    const float4* Wr = W4 + (size_t)(sec*3+1)*2048 + h;
    float yz0[2]={},yz1[2]={},yz2[2]={},yz3[2]={};
    float yr0[2]={},yr1[2]={},yr2[2]={},yr3[2]={};
    for (int c=0;c<C;c++){
        float4 wz = Wz[c*32];
        float4 wr = Wr[c*32];
        #pragma unroll
        for (int bb=0;bb<2;bb++){
            int bl = bt*2+bb;
            float x0=sX[0][c][bl], x1r=sX[1][c][bl], x1i=sX[2][c][bl], x2=sX[3][c][bl];
            yz0[bb]+=x0*wz.x; yz1[bb]+=x1r*wz.y - x1i*wz.z;
            yz2[bb]+=x1r*wz.z + x1i*wz.y; yz3[bb]+=x2*wz.w;
            yr0[bb]+=x0*wr.x; yr1[bb]+=x1r*wr.y - x1i*wr.z;
            yr2[bb]+=x1r*wr.z + x1i*wr.y; yr3[bb]+=x2*wr.w;
        }
    }
    float bz[4], br[4];
    #pragma unroll
    for (int r=0;r<4;r++){ bz[r]=bias[h*4+r]; br[r]=bias[128+h*4+r]; }
    float* Z = g_Z + (size_t)sec*HSZ;
    const size_t GS = (size_t)NP*2048;
    #pragma unroll
    for (int bb=0;bb<2;bb++){
        int b = bgBase + bt*2 + bb;
        float vz[4] = {0.25f*(yz0[bb]+yz3[bb]+2.f*yz1[bb]), 0.25f*(yz0[bb]-yz3[bb]-2.f*yz2[bb]),
                       0.25f*(yz0[bb]+yz3[bb]-2.f*yz1[bb]), 0.25f*(yz0[bb]-yz3[bb]+2.f*yz2[bb])};
        float vr[4] = {0.25f*(yr0[bb]+yr3[bb]+2.f*yr1[bb]), 0.25f*(yr0[bb]-yr3[bb]-2.f*yr2[bb]),
                       0.25f*(yr0[bb]+yr3[bb]-2.f*yr1[bb]), 0.25f*(yr0[bb]-yr3[bb]+2.f*yr2[bb])};
        size_t hoff = (((size_t)b*Nn + n)*Hh + h)*4;
        float4 hs4 = Hs ? *reinterpret_cast<const float4*>(Hs + hoff) : make_float4(0,0,0,0);
        float hsv[4] = {hs4.x,hs4.y,hs4.z,hs4.w};
        float g[4], zv[4];
        #pragma unroll
        for (int r=0;r<4;r++){
            zv[r] = fsig(vz[r] + bz[r]);
            float rg = fsig(vr[r] + br[r]);
            g[r] = rg*hsv[r];
        }
        *reinterpret_cast<float4*>(Z + hoff) = make_float4(zv[0],zv[1],zv[2],zv[3]);
        size_t gb = (size_t)n*2048 + gcol + b*Hh + h;
        float s1 = g[0]-g[2], s2 = g[3]-g[1];
        g_Gf[0*GS + gb] = g[0]+g[1]+g[2]+g[3];
        g_Gf[1*GS + gb] = s1;
        g_Gf[2*GS + gb] = s2;
        g_Gf[3*GS + gb] = g[0]-g[1]+g[2]-g[3];
        g_Gf[4*GS + gb] = s1 + s2;
    }
}

// ---------------------------------------------------------------------------
// Ht: grid (Nn, nSec, 4 batch groups), block (32,4). Thread handles 2 batches.
// ---------------------------------------------------------------------------
__global__ void ht6_kernel(int secBase, int t,
    const float* __restrict__ HsA, const float* __restrict__ biasA,
    float* __restrict__ HnewA, float* __restrict__ outA, float* __restrict__ tailA,
    const float* __restrict__ HsB, const float* __restrict__ biasB,
    float* __restrict__ HnewB, float* __restrict__ outB, float* __restrict__ tailB)
{
    cudaGridDependencySynchronize();
    int n = blockIdx.x;
    int sec = secBase + blockIdx.y;
    int bgBase = blockIdx.z * 8;
    const float* Hs   = blockIdx.y ? HsB : HsA;
    const float* bias = blockIdx.y ? biasB : biasA;
    float* Hnew = blockIdx.y ? HnewB : HnewA;
    float* outp = blockIdx.y ? outB : outA;
    float* tailp= blockIdx.y ? tailB : tailA;
    int Fin  = sec ? 32 : 16;
    int gcol = sec ? 1024 : 0;
    int hbase= sec ? 1024 : 0;

    __shared__ float sXx[4][32][9];
    __shared__ float sG[4][32][9];
    int tid = threadIdx.y*32 + threadIdx.x;
    const size_t SS = (size_t)RP*JB;
    const size_t AS = (size_t)RP*JG;
    const float* AX = g_AXH + (size_t)n*JB;
    const float* AG = g_AG + (size_t)n*JG + gcol;
    for (int i=tid;i<4*Fin*8;i+=128){
        int c = i % Fin; int r = i / Fin; int s = r >> 3; int bl = r & 7;
        int b = bgBase + bl;
        int col = (sec==0) ? (b*16+c) : (512 + b*32 + c);
        float v;
        if (s==0)      v = AX[col];
        else if (s==1) v = AX[SS+col] - AX[2*SS+col];
        else if (s==2) v = AX[4*SS+col] - AX[SS+col] - AX[2*SS+col];
        else           v = AX[3*SS+col];
        sXx[s][c][bl] = v;
    }
    for (int i=tid;i<4*32*8;i+=128){
        int c = i & 31; int r = i >> 5; int s = r >> 3; int bl = r & 7;
        int b = bgBase + bl;
        int col = b*Hh + c;
        float v;
        if (s==0)      v = AG[col];
        else if (s==1) v = AG[AS+col] - AG[2*AS+col];
        else if (s==2) v = AG[4*AS+col] - AG[AS+col] - AG[2*AS+col];
        else           v = AG[3*AS+col];
        sG[s][c][bl] = v;
    }
    __syncthreads();

    int h = threadIdx.x, bt = threadIdx.y;
    const float4* Wh = reinterpret_cast<const float4*>(g_W) + (size_t)(sec*3+2)*2048 + h;
    float y0[2]={},y1[2]={},y2[2]={},y3[2]={};
    for (int c=0;c<Fin;c++){
        float4 w = Wh[c*32];
        #pragma unroll
        for (int bb=0;bb<2;bb++){
            int bl = bt*2+bb;
            float x0=sXx[0][c][bl], x1r=sXx[1][c][bl], x1i=sXx[2][c][bl], x2=sXx[3][c][bl];
            y0[bb]+=x0*w.x; y1[bb]+=x1r*w.y - x1i*w.z;
            y2[bb]+=x1r*w.z + x1i*w.y; y3[bb]+=x2*w.w;
        }
    }
    for (int c=0;c<Hh;c++){
        float4 w = Wh[(Fin+c)*32];
        #pragma unroll
        for (int bb=0;bb<2;bb++){
            int bl = bt*2+bb;
            float x0=sG[0][c][bl], x1r=sG[1][c][bl], x1i=sG[2][c][bl], x2=sG[3][c][bl];
            y0[bb]+=x0*w.x; y1[bb]+=x1r*w.y - x1i*w.z;
            y2[bb]+=x1r*w.z + x1i*w.y; y3[bb]+=x2*w.w;
        }
    }
    float bh[4];
    #pragma unroll
    for (int r=0;r<4;r++) bh[r] = bias[256 + h*4 + r];
    const float* Z = g_Z + (size_t)sec*HSZ;
    const size_t HS2 = (size_t)NP*2048;
    #pragma unroll
    for (int bb=0;bb<2;bb++){
        int b = bgBase + bt*2 + bb;
        float v[4] = {0.25f*(y0[bb]+y3[bb]+2.f*y1[bb]), 0.25f*(y0[bb]-y3[bb]-2.f*y2[bb]),
                      0.25f*(y0[bb]+y3[bb]-2.f*y1[bb]), 0.25f*(y0[bb]-y3[bb]+2.f*y2[bb])};
        size_t hoff = (((size_t)b*Nn+n)*Hh + h)*4;
        float4 z4 = *reinterpret_cast<const float4*>(Z + hoff);
        float zv[4] = {z4.x,z4.y,z4.z,z4.w};
        float4 hs4 = Hs ? *reinterpret_cast<const float4*>(Hs + hoff) : make_float4(0,0,0,0);
        float hsv[4] = {hs4.x,hs4.y,hs4.z,hs4.w};
        float hn[4];
        #pragma unroll
        for (int r=0;r<4;r++){
            float ht = ftanh(v[r] + bh[r]);
            hn[r] = zv[r]*hsv[r] + (1.f-zv[r])*ht;
        }
        float4 hv = make_float4(hn[0],hn[1],hn[2],hn[3]);
        *reinterpret_cast<float4*>(Hnew + hoff) = hv;
        if (outp)
            *reinterpret_cast<float4*>(outp + (((size_t)b*Tt + t)*Nn + n)*(Hh*4) + h*4) = hv;
        if (tailp)
            *reinterpret_cast<float4*>(tailp + hoff) = hv;
        size_t hb = (size_t)n*2048 + hbase + b*Hh + h;
        float s1 = hn[0]-hn[2], s2 = hn[3]-hn[1];
        g_Hf[0*HS2 + hb] = hn[0]+hn[1]+hn[2]+hn[3];
        g_Hf[1*HS2 + hb] = s1;
        g_Hf[2*HS2 + hb] = s2;
        g_Hf[3*HS2 + hb] = hn[0]-hn[1]+hn[2]-hn[3];
        g_Hf[4*HS2 + hb] = s1 + s2;
    }
}

// ---------------------------------------------------------------------------
template <typename K, typename... Args>
static inline void pdl(K kern, dim3 g, dim3 b, Args... args){
    cudaLaunchConfig_t cfg = {};
    cfg.gridDim = g;
    cfg.blockDim = b;
    cfg.dynamicSmemBytes = 0;
    cfg.stream = 0;
    cudaLaunchAttribute attr[1];
    attr[0].id = cudaLaunchAttributeProgrammaticStreamSerialization;
    attr[0].val.programmaticStreamSerializationAllowed = 1;
    cfg.attrs = attr;
    cfg.numAttrs = 1;
    cudaLaunchKernelEx(&cfg, kern, args...);
}

// ---------------------------------------------------------------------------
extern "C" void kernel_launch(void* const* d_in, const int* in_sizes, int n_in,
                              void* d_out, int out_size) {
    (void)in_sizes; (void)n_in;
    const float* inputs = (const float*)d_in[0];
    const float* U      = (const float*)d_in[1];
    const float* B0p    = (const float*)d_in[7];
    const float* B1p    = (const float*)d_in[13];
    float* out = (float*)d_out;
    const int OUTSZ = Bb*Tt*Nn*Hh*Rr;
    float* tail = (out_size >= OUTSZ + 2*HSZ) ? (out + OUTSZ) : nullptr;

    void* p;
    cudaGetSymbolAddress(&p, g_At);   float* Atp  = (float*)p;
    cudaGetSymbolAddress(&p, g_Xall); float* Xall = (float*)p;
    cudaGetSymbolAddress(&p, g_Hf);   float* Hf   = (float*)p;
    cudaGetSymbolAddress(&p, g_AXH);  float* AXH  = (float*)p;
    cudaGetSymbolAddress(&p, g_Gf);   float* Gfp  = (float*)p;
    cudaGetSymbolAddress(&p, g_AG);   float* AG   = (float*)p;
    cudaGetSymbolAddress(&p, g_H);    float* Hb   = (float*)p;
    float* H0[2] = {Hb,          Hb +   HSZ};
    float* H1[2] = {Hb + 2*HSZ,  Hb + 3*HSZ};

    cudaMemsetAsync(Atp,  0, sizeof(float)*5*NP*NR);
    cudaMemsetAsync(Xall, 0, sizeof(float)*5*Tt*NP*512);
    cudaMemsetAsync(Hf,   0, sizeof(float)*5*NP*2048);
    cudaMemsetAsync(Gfp,  0, sizeof(float)*5*NP*2048);
    cudaMemsetAsync(AG,   0, sizeof(float)*5*RP*JG);
    cudaMemsetAsync(AXH,  0, sizeof(float)*5*RP*JB);

    pdl(adj_kernel, dim3(Nn), dim3(256), U);
    pdl(wprep_kernel, dim3(48), dim3(256),
        (const float*)d_in[2], (const float*)d_in[3], (const float*)d_in[4],
        (const float*)d_in[5], (const float*)d_in[6],
        (const float*)d_in[8], (const float*)d_in[9], (const float*)d_in[10],
        (const float*)d_in[11], (const float*)d_in[12]);
    pdl(xprep_kernel, dim3((Tt*Nn*512+255)/256), dim3(256), inputs);

    const size_t XSST = (size_t)Tt*XT;
    const size_t HSST = (size_t)NP*2048;
    const size_t AXS  = (size_t)RP*JB;
    const size_t AGS  = (size_t)RP*JG;
    dim3 blkG(32,4);

    // ---- t = 0, layer0 (H cols of AXH zero via memset) ----
    pdl(agg6_kernel, dim3(8,3,5), dim3(256),
        (const float*)Xall, 512, XSST, 512, (const float*)Hf, (int)JG, HSST,
        AXH, (int)JB, AXS, 0);
    pdl(gates6_kernel, dim3(Nn,1,4), blkG,
        0, (const float*)nullptr, B0p, (const float*)nullptr, B0p);
    pdl(ht6_kernel, dim3(Nn,1,4), blkG,
        0, 0,
        (const float*)nullptr, B0p, H0[1], (float*)nullptr, (float*)nullptr,
        (const float*)nullptr, B0p, H0[1], (float*)nullptr, (float*)nullptr);
    // A @ fft(H0(t0)) for layer1's t0 input (cols 512..1536 -> tiles 8..23)
    pdl(agg6_kernel, dim3(16,3,5), dim3(256),
        (const float*)Xall, 512, XSST, 512, (const float*)Hf, (int)JG, HSST,
        AXH, (int)JB, AXS, 8);
    pdl(gates6_kernel, dim3(Nn,1,4), blkG,
        1, (const float*)nullptr, B1p, (const float*)nullptr, B1p);
    pdl(ht6_kernel, dim3(Nn,1,4), blkG,
        1, 0,
        (const float*)nullptr, B1p, H1[1], out, (float*)nullptr,
        (const float*)nullptr, B1p, H1[1], out, (float*)nullptr);

    // ---- t = 1..7 ----
    int c0 = 1, c1 = 1;
    for (int t=1; t<Tt; t++){
        float* tl0 = (t==Tt-1 && tail) ? tail        : nullptr;
        float* tl1 = (t==Tt-1 && tail) ? tail + HSZ  : nullptr;
        const float* Xt = Xall + (size_t)t*XT;
        pdl(agg6_kernel, dim3(40,3,5), dim3(256),
            Xt, 512, XSST, 512, (const float*)Hf, (int)JG, HSST,
            AXH, (int)JB, AXS, 0);
        pdl(gates6_kernel, dim3(Nn,2,4), blkG,
            0, (const float*)H0[c0], B0p, (const float*)H1[c1], B1p);
        pdl(agg6_kernel, dim3(32,3,5), dim3(256),
            (const float*)Gfp, (int)JG, HSST, (1<<30), (const float*)Gfp, (int)JG, HSST,
            AG, (int)JG, AGS, 0);
        pdl(ht6_kernel, dim3(Nn,2,4), blkG,
            0, t,
            (const float*)H0[c0], B0p, H0[c0^1], (float*)nullptr, tl0,
            (const float*)H1[c1], B1p, H1[c1^1], out,             tl1);
        c0 ^= 1; c1 ^= 1;
    }
}